// round 2
// baseline (speedup 1.0000x reference)
#include <cuda_runtime.h>
#include <cuda_bf16.h>

// GroupTokenizer: y[B,T,C] fp32, left/right edges [C,K] fp32.
// Output buffer (fp32): [ labels(B*T*C) | reg(B*T*C*K) ].
// B=32, T=4096, C=8, K=64.

#define KBINS 64
#define CCH 8
#define ESTR 65            // padded shared stride to avoid bank conflicts
#define TPB 256            // threads per block == elements per block
#define EPSW 1e-12f

__global__ void __launch_bounds__(TPB)
gt_kernel(const float* __restrict__ y,
          const float* __restrict__ le,
          const float* __restrict__ re,
          float* __restrict__ out_labels,
          float* __restrict__ out_reg)
{
    __shared__ float s_l[CCH * ESTR];
    __shared__ float s_r[CCH * ESTR];
    __shared__ float s_delta[TPB];
    __shared__ int   s_lab[TPB];

    const int tid = threadIdx.x;

    // Load edge tables into shared (padded stride).
    #pragma unroll
    for (int i = tid; i < CCH * KBINS; i += TPB) {
        int c = i >> 6;          // i / KBINS
        int k = i & (KBINS - 1); // i % KBINS
        s_l[c * ESTR + k] = le[i];
        s_r[c * ESTR + k] = re[i];
    }
    __syncthreads();

    const int base = blockIdx.x * TPB;
    const int idx  = base + tid;     // flattened (b,t,c); grid sized exactly

    // ---------------- Phase 1: label + delta per element ----------------
    const float yv = y[idx];
    const int   c  = idx & (CCH - 1);          // channel = fastest dim
    const float* lrow = s_l + c * ESTR;
    const float* rrow = s_r + c * ESTR;

    // Branchless lower-bound: pos = first k with r[k] > yv (r non-decreasing).
    // Offset search: exactly 6 steps for K=64, probe indices always <= 63.
    int pos = 0;
    #pragma unroll
    for (int step = 32; step >= 1; step >>= 1) {
        if (rrow[pos + step - 1] <= yv) pos += step;
    }
    // pos in [0,64]. Bins are contiguous (r[k] == l[k+1]), so the first
    // containing bin (reference argmax of in_bin) is pos iff yv >= l[pos].
    int label = (pos < KBINS && yv >= lrow[pos]) ? pos : (KBINS - 1);

    // Delta from the selected label even when out-of-range (reference gathers
    // left/right at `labels` unconditionally).
    float ll = lrow[label];
    float rr = rrow[label];
    float w  = fmaxf(rr - ll, EPSW);
    float d  = (yv - ll) / w;
    d = fminf(fmaxf(d, 0.0f), 1.0f);

    out_labels[idx] = (float)label;   // coalesced
    s_lab[tid]   = label;
    s_delta[tid] = d;
    __syncthreads();

    // ---------------- Phase 2: coalesced reg tile writes ----------------
    // Block writes TPB*K floats = 64 KB, as float4s, consecutive across lanes.
    float4* regv = reinterpret_cast<float4*>(out_reg + (size_t)base * KBINS);
    const int kbase = (tid & 15) * 4;   // fixed K-offset handled by this thread
    const int e0    = tid >> 4;         // starting element within the block

    #pragma unroll
    for (int i = 0; i < 16; i++) {
        int   e   = e0 + i * 16;        // element index in [0,256)
        int   lab = s_lab[e];           // broadcast within half-warp groups
        float dd  = s_delta[e];
        float4 v;
        v.x = (lab == kbase + 0) ? dd : -1.0f;
        v.y = (lab == kbase + 1) ? dd : -1.0f;
        v.z = (lab == kbase + 2) ? dd : -1.0f;
        v.w = (lab == kbase + 3) ? dd : -1.0f;
        regv[tid + i * TPB] = v;        // fully coalesced STG.128
    }
}

extern "C" void kernel_launch(void* const* d_in, const int* in_sizes, int n_in,
                              void* d_out, int out_size)
{
    const float* y  = (const float*)d_in[0];
    const float* le = (const float*)d_in[1];
    const float* re = (const float*)d_in[2];
    float* out = (float*)d_out;

    const int n = in_sizes[0];          // B*T*C = 1048576 (multiple of TPB)
    float* out_labels = out;
    float* out_reg    = out + (size_t)n;

    const int blocks = n / TPB;
    gt_kernel<<<blocks, TPB>>>(y, le, re, out_labels, out_reg);
}